// round 2
// baseline (speedup 1.0000x reference)
#include <cuda_runtime.h>
#include <cstdint>

// Fused: conv3x3 (zero-pad bottom/right) -> +bias -> *scale -> maxpool2x2 -> clamp[0,1]
// x: [B,3,512,512] f32, w: [16,3,3,3], bias: [16], scale: [16,1,1]
// out: [B,16,256,256] f32
//
// One thread computes one pooled pixel for all 16 OC using packed f32x2 FMA
// (two horizontal conv columns per lane-pair -> 2 FMA/instr, 128 FMA/cyc/SM).

#define OCN 16
#define ICN 3
#define IH 512
#define IW 512
#define PH 256
#define PW 256

__device__ __forceinline__ unsigned long long pack2(float a, float b) {
    unsigned long long r;
    asm("mov.b64 %0, {%1, %2};" : "=l"(r) : "f"(a), "f"(b));
    return r;
}
__device__ __forceinline__ void unpack2(unsigned long long p, float& a, float& b) {
    asm("mov.b64 {%0, %1}, %2;" : "=f"(a), "=f"(b) : "l"(p));
}
__device__ __forceinline__ void fma2(unsigned long long& acc, unsigned long long a,
                                     unsigned long long b) {
    asm("fma.rn.f32x2 %0, %1, %2, %0;" : "+l"(acc) : "l"(a), "l"(b));
}
// d = a*b + c (non-accumulating form, for the bias/scale epilogue)
__device__ __forceinline__ unsigned long long fma2n(unsigned long long a, unsigned long long b,
                                                    unsigned long long c) {
    unsigned long long d;
    asm("fma.rn.f32x2 %0, %1, %2, %3;" : "=l"(d) : "l"(a), "l"(b), "l"(c));
    return d;
}

__global__ __launch_bounds__(128)
void conv_pool_clamp_kernel(const float* __restrict__ x,
                            const float* __restrict__ w,
                            const float* __restrict__ bias,
                            const float* __restrict__ scale,
                            float* __restrict__ out) {
    // Weights pre-duplicated {w,w} as 64-bit words for direct LDS.64 broadcast.
    __shared__ unsigned long long sw[OCN * ICN * 9];
    __shared__ unsigned long long ssc[OCN];   // {s, s}
    __shared__ unsigned long long sbs[OCN];   // {b*s, b*s}

    const int tid = threadIdx.x;
    for (int i = tid; i < OCN * ICN * 9; i += blockDim.x) {
        float v = w[i];
        sw[i] = pack2(v, v);
    }
    if (tid < OCN) {
        float s = scale[tid];
        float bs = bias[tid] * s;
        ssc[tid] = pack2(s, s);
        sbs[tid] = pack2(bs, bs);
    }
    __syncthreads();

    const int pw = blockIdx.x * blockDim.x + tid;   // 0..255
    const int ph = blockIdx.y;                      // 0..255
    const int bi = blockIdx.z;                      // 0..B-1
    if (pw >= PW) return;

    const int ih0 = ph * 2;
    const int iw0 = pw * 2;

    // Accumulators: per OC, top conv row (oh=2ph) and bottom conv row (oh=2ph+1),
    // each holding conv columns {2pw, 2pw+1} packed in f32x2.
    unsigned long long acc_t[OCN], acc_b[OCN];
#pragma unroll
    for (int o = 0; o < OCN; o++) { acc_t[o] = 0ull; acc_b[o] = 0ull; }

#pragma unroll
    for (int ic = 0; ic < ICN; ic++) {
        const float* xc = x + ((size_t)bi * ICN + ic) * (IH * IW);

        // 4x4 input patch, zero-padded bottom/right.
        float r[4][4];
#pragma unroll
        for (int rr = 0; rr < 4; rr++) {
            const int ih = ih0 + rr;
            float c0 = 0.f, c1 = 0.f, c2 = 0.f, c3 = 0.f;
            if (ih < IH) {
                const float* row = xc + (size_t)ih * IW;
                // cols iw0, iw0+1 always in-bounds (iw0 <= 510)
                float2 lo = *(const float2*)(row + iw0);
                c0 = lo.x; c1 = lo.y;
                if (iw0 + 2 < IW) {   // iw0 even: hi pair fully in or fully out
                    float2 hi = *(const float2*)(row + iw0 + 2);
                    c2 = hi.x; c3 = hi.y;
                }
            }
            r[rr][0] = c0; r[rr][1] = c1; r[rr][2] = c2; r[rr][3] = c3;
        }

        // Overlapping column pairs per row: p[rr][t] = {r[rr][t], r[rr][t+1]}
        unsigned long long p[4][3];
#pragma unroll
        for (int rr = 0; rr < 4; rr++) {
#pragma unroll
            for (int t = 0; t < 3; t++) p[rr][t] = pack2(r[rr][t], r[rr][t + 1]);
        }

#pragma unroll
        for (int oc = 0; oc < OCN; oc++) {
            const unsigned long long* wp = &sw[(oc * ICN + ic) * 9];
#pragma unroll
            for (int kh = 0; kh < 3; kh++) {
#pragma unroll
                for (int kw = 0; kw < 3; kw++) {
                    const unsigned long long w2 = wp[kh * 3 + kw];  // LDS.64 broadcast
                    fma2(acc_t[oc], p[kh][kw], w2);      // conv row oh = 2ph
                    fma2(acc_b[oc], p[kh + 1][kw], w2);  // conv row oh = 2ph+1
                }
            }
        }
    }

    // Epilogue: (y + bias) * scale  ->  max over 2x2  ->  clamp [0,1]
    float* ob = out + (((size_t)bi * OCN) * PH + ph) * PW + pw;
#pragma unroll
    for (int oc = 0; oc < OCN; oc++) {
        unsigned long long t = fma2n(acc_t[oc], ssc[oc], sbs[oc]);
        unsigned long long b = fma2n(acc_b[oc], ssc[oc], sbs[oc]);
        float t0, t1, b0, b1;
        unpack2(t, t0, t1);
        unpack2(b, b0, b1);
        float m = fmaxf(fmaxf(t0, t1), fmaxf(b0, b1));
        m = fminf(fmaxf(m, 0.0f), 1.0f);
        ob[(size_t)oc * (PH * PW)] = m;
    }
}

extern "C" void kernel_launch(void* const* d_in, const int* in_sizes, int n_in,
                              void* d_out, int out_size) {
    const float* x     = (const float*)d_in[0];
    const float* w     = (const float*)d_in[1];
    const float* bias  = (const float*)d_in[2];
    const float* scale = (const float*)d_in[3];
    float* out = (float*)d_out;

    const int B = in_sizes[0] / (ICN * IH * IW);   // 32

    dim3 block(128);
    dim3 grid(PW / 128, PH, B);
    conv_pool_clamp_kernel<<<grid, block>>>(x, w, bias, scale, out);
}